// round 3
// baseline (speedup 1.0000x reference)
#include <cuda_runtime.h>
#include <math.h>

#define BB   16384
#define INF  256
#define HH   256
#define OUTF 256
#define LL   7
#define G4   (4 * HH)   // 1024

// 67 MB scratch for one layer's gates [B, 4H] (reused across the 8 layers)
__device__ float g_gates[(size_t)BB * G4];

// C[m,n] = sum_k A1[m,k]*W1[n,k] (+ sum_k A2[m,k]*W2[n,k]) + bias1[n] (+ bias2[n])
// A: [M,K] row-major, W: [N,K] row-major (both K-contiguous -> TN gemm).
// Tile 64x64, BK=16, 256 threads, 4x4 per-thread microtile. Dims assumed multiples of 64/16.
__global__ void __launch_bounds__(256) gemm_tn_kernel(
    const float* __restrict__ A1, const float* __restrict__ W1, int K1,
    const float* __restrict__ A2, const float* __restrict__ W2, int K2,
    const float* __restrict__ bias1, const float* __restrict__ bias2,
    float* __restrict__ C, int N)
{
    __shared__ float As[16][68];   // [k][m], padded: float4 reads stay 16B-aligned
    __shared__ float Ws[16][68];   // [k][n]

    const int bm  = blockIdx.y * 64;
    const int bn  = blockIdx.x * 64;
    const int tid = threadIdx.x;
    const int tx  = tid & 15;      // n sub-tile
    const int ty  = tid >> 4;      // m sub-tile
    const int lrow = tid >> 2;     // 0..63  (tile row loaded by this thread)
    const int lk   = (tid & 3) << 2; // 0,4,8,12 (k offset, one float4)

    float acc[4][4] = {};

    #pragma unroll 1
    for (int pass = 0; pass < 2; ++pass) {
        const float* A = pass ? A2 : A1;
        const float* W = pass ? W2 : W1;
        const int    K = pass ? K2 : K1;
        if (A == nullptr) break;

        const float* aptr = A + (size_t)(bm + lrow) * K + lk;
        const float* wptr = W + (size_t)(bn + lrow) * K + lk;

        for (int k0 = 0; k0 < K; k0 += 16) {
            float4 av = *(const float4*)(aptr + k0);
            float4 wv = *(const float4*)(wptr + k0);
            __syncthreads();   // previous iter's reads done before overwrite
            As[lk + 0][lrow] = av.x; As[lk + 1][lrow] = av.y;
            As[lk + 2][lrow] = av.z; As[lk + 3][lrow] = av.w;
            Ws[lk + 0][lrow] = wv.x; Ws[lk + 1][lrow] = wv.y;
            Ws[lk + 2][lrow] = wv.z; Ws[lk + 3][lrow] = wv.w;
            __syncthreads();
            #pragma unroll
            for (int k = 0; k < 16; ++k) {
                float4 a4 = *(const float4*)&As[k][ty << 2];
                float4 w4 = *(const float4*)&Ws[k][tx << 2];
                float ar[4] = {a4.x, a4.y, a4.z, a4.w};
                float wr[4] = {w4.x, w4.y, w4.z, w4.w};
                #pragma unroll
                for (int i = 0; i < 4; ++i)
                    #pragma unroll
                    for (int j = 0; j < 4; ++j)
                        acc[i][j] = fmaf(ar[i], wr[j], acc[i][j]);
            }
        }
    }

    float bv[4];
    #pragma unroll
    for (int j = 0; j < 4; ++j) {
        int n = bn + (tx << 2) + j;
        float b = bias1 ? bias1[n] : 0.0f;
        if (bias2) b += bias2[n];
        bv[j] = b;
    }
    #pragma unroll
    for (int i = 0; i < 4; ++i) {
        float4 v;
        v.x = acc[i][0] + bv[0];
        v.y = acc[i][1] + bv[1];
        v.z = acc[i][2] + bv[2];
        v.w = acc[i][3] + bv[3];
        *(float4*)&C[(size_t)(bm + (ty << 2) + i) * N + bn + (tx << 2)] = v;
    }
}

__device__ __forceinline__ float sigf(float x) {
    return 1.0f / (1.0f + __expf(-x));
}

// Per-element LSTM gating: gates [B,4H] (i,f,g,o blocks), c_in [B,H] -> h_out, c_out [B,H]
__global__ void __launch_bounds__(256) gate_kernel(
    const float* __restrict__ gates, const float* __restrict__ c_in,
    float* __restrict__ h_out, float* __restrict__ c_out)
{
    int idx = blockIdx.x * blockDim.x + threadIdx.x;   // over B*H
    if (idx >= BB * HH) return;
    int b   = idx >> 8;          // H == 256
    int col = idx & 255;
    const float* g = gates + (size_t)b * G4;
    float gi = sigf(g[col]);
    float gf = sigf(g[col + HH]);
    float gg = tanhf(g[col + 2 * HH]);
    float go = sigf(g[col + 3 * HH]);
    float c  = gf * c_in[idx] + gi * gg;
    c_out[idx] = c;
    h_out[idx] = go * tanhf(c);
}

extern "C" void kernel_launch(void* const* d_in, const int* in_sizes, int n_in,
                              void* d_out, int out_size)
{
    const float* x     = (const float*)d_in[0];
    const float* h_all = (const float*)d_in[1];
    const float* c_all = (const float*)d_in[2];
    const float* Wih0  = (const float*)d_in[3];
    const float* Whh0  = (const float*)d_in[4];
    const float* bih0  = (const float*)d_in[5];
    const float* bhh0  = (const float*)d_in[6];
    const float* Wih   = (const float*)d_in[7];
    const float* Whh   = (const float*)d_in[8];
    const float* bih   = (const float*)d_in[9];
    const float* bhh   = (const float*)d_in[10];
    const float* Wout  = (const float*)d_in[11];
    const float* bout  = (const float*)d_in[12];

    float* out = (float*)d_out;                       // [B, OUT]
    float* hs  = out + (size_t)BB * OUTF;             // [L+1, B, H]
    float* cs  = hs + (size_t)(LL + 1) * BB * HH;     // [L+1, B, H]

    float* gates = nullptr;
    cudaGetSymbolAddress((void**)&gates, g_gates);

    const dim3 blk(256);
    const dim3 grid_g(G4 / 64, BB / 64);      // 16 x 256 tiles
    const dim3 grid_o(OUTF / 64, BB / 64);    // 4 x 256 tiles
    const int  gate_blocks = (BB * HH + 255) / 256;

    for (int l = 0; l <= LL; ++l) {
        const float* xin = (l == 0) ? x    : hs + (size_t)(l - 1) * BB * HH;
        const float* Wi  = (l == 0) ? Wih0 : Wih + (size_t)(l - 1) * G4 * HH;
        const float* Wh  = (l == 0) ? Whh0 : Whh + (size_t)(l - 1) * G4 * HH;
        const float* bi  = (l == 0) ? bih0 : bih + (size_t)(l - 1) * G4;
        const float* bh  = (l == 0) ? bhh0 : bhh + (size_t)(l - 1) * G4;
        const int    Kx  = (l == 0) ? INF  : HH;
        const float* hst = h_all + (size_t)l * BB * HH;
        const float* cst = c_all + (size_t)l * BB * HH;

        gemm_tn_kernel<<<grid_g, blk>>>(xin, Wi, Kx, hst, Wh, HH, bi, bh, gates, G4);
        gate_kernel<<<gate_blocks, blk>>>(gates, cst,
                                          hs + (size_t)l * BB * HH,
                                          cs + (size_t)l * BB * HH);
    }

    // output = h_last @ Wout.T + bout
    gemm_tn_kernel<<<grid_o, blk>>>(hs + (size_t)LL * BB * HH, Wout, HH,
                                    nullptr, nullptr, 0,
                                    bout, nullptr, out, OUTF);
}

// round 5
// speedup vs baseline: 2.6651x; 2.6651x over previous
#include <cuda_runtime.h>
#include <cuda_bf16.h>
#include <stdint.h>
#include <math.h>

#define BB   16384
#define HH   256
#define OUTF 256
#define LL   7
#define G4   1024
#define KT   512

// ---------------- scratch (__device__ globals; no allocs allowed) ----------------
__device__ __align__(256) float          g_gates[(size_t)BB * G4];            // 67 MB
__device__ __align__(256) __nv_bfloat16  g_ahi[(size_t)BB * KT];              // activations hi [B,512]
__device__ __align__(256) __nv_bfloat16  g_alo[(size_t)BB * KT];              // activations lo
__device__ __align__(256) __nv_bfloat16  g_whi[(size_t)(LL + 1) * G4 * KT];   // weights hi [8][1024][512]
__device__ __align__(256) __nv_bfloat16  g_wlo[(size_t)(LL + 1) * G4 * KT];
__device__ __align__(256) __nv_bfloat16  g_wouthi[HH * HH];
__device__ __align__(256) __nv_bfloat16  g_woutlo[HH * HH];

// ---------------- PTX helpers (all arch-portable: sm_80/90 baseline) ----------------
__device__ __forceinline__ uint32_t smem_u32(const void* p) {
    uint32_t a;
    asm("{ .reg .u64 t; cvta.to.shared.u64 t, %1; cvt.u32.u64 %0, t; }" : "=r"(a) : "l"(p));
    return a;
}
__device__ __forceinline__ void cp16(uint32_t s, const void* g) {
    asm volatile("cp.async.cg.shared.global [%0], [%1], 16;" :: "r"(s), "l"(g));
}
__device__ __forceinline__ void ldmatrix_x4(uint32_t r[4], uint32_t addr) {
    asm volatile("ldmatrix.sync.aligned.m8n8.x4.shared.b16 {%0,%1,%2,%3}, [%4];"
        : "=r"(r[0]), "=r"(r[1]), "=r"(r[2]), "=r"(r[3]) : "r"(addr));
}
__device__ __forceinline__ void mma16816(float c[4], const uint32_t a[4],
                                         uint32_t b0, uint32_t b1) {
    asm volatile("mma.sync.aligned.m16n8k16.row.col.f32.bf16.bf16.f32 "
        "{%0,%1,%2,%3}, {%4,%5,%6,%7}, {%8,%9}, {%0,%1,%2,%3};"
        : "+f"(c[0]), "+f"(c[1]), "+f"(c[2]), "+f"(c[3])
        : "r"(a[0]), "r"(a[1]), "r"(a[2]), "r"(a[3]), "r"(b0), "r"(b1));
}

// ---------------- split-bf16 TN GEMM via mma.sync (HMMA) ----------------
// C[m,n] = sum_k (Ahi+Alo)[m,k]*(Bhi+Blo)[n,k]  (3 passes: hi*hi, lo*hi, hi*lo)
#define TM 256
#define TN 128
#define NTHREADS 512
#define STAGE_A (TM * 128)                 // 32 KB (256 rows x 64 bf16)
#define STAGE_B (TN * 128)                 // 16 KB
#define STAGE   (STAGE_A + STAGE_B)        // 48 KB
#define SMEMSZ  (2 * STAGE)                // 96 KB

__global__ void __launch_bounds__(NTHREADS, 1) mma_gemm(
    const __nv_bfloat16* __restrict__ Ahi, const __nv_bfloat16* __restrict__ Alo, int sA,
    const __nv_bfloat16* __restrict__ Bhi, const __nv_bfloat16* __restrict__ Blo, int sB,
    int Ktot, const float* __restrict__ bias, float* __restrict__ C, int sC)
{
    extern __shared__ __align__(128) char dsm[];
    const int tid  = threadIdx.x;
    const int lane = tid & 31;
    const int wid  = tid >> 5;
    const int wm   = wid & 3;        // 4 warps along M (64 each)
    const int wn   = wid >> 2;       // 4 warps along N (32 each)
    const int m0   = blockIdx.y * TM;
    const int n0   = blockIdx.x * TN;
    const uint32_t sbase = smem_u32(dsm);

    const int nchunks = Ktot >> 6;   // BK = 64
    const int niter   = 3 * nchunks;

    float c[4][4][4];
    #pragma unroll
    for (int i = 0; i < 4; ++i)
        #pragma unroll
        for (int j = 0; j < 4; ++j)
            #pragma unroll
            for (int q = 0; q < 4; ++q) c[i][j][q] = 0.0f;

    auto load_stage = [&](int buf, int iter) {
        const int p  = iter / nchunks;
        const int kc = (iter - p * nchunks) << 6;
        const __nv_bfloat16* Ap = (p == 1) ? Alo : Ahi;
        const __nv_bfloat16* Bp = (p == 2) ? Blo : Bhi;
        const uint32_t sa = sbase + buf * STAGE;
        const uint32_t sb = sa + STAGE_A;
        #pragma unroll
        for (int i = 0; i < 4; ++i) {                    // A: 256 rows x 8 chunks
            int idx = tid + i * NTHREADS;
            int row = idx >> 3, kg = idx & 7;
            cp16(sa + row * 128 + (((kg ^ (row & 7))) << 4),
                 Ap + (size_t)(m0 + row) * sA + kc + kg * 8);
        }
        #pragma unroll
        for (int i = 0; i < 2; ++i) {                    // B: 128 rows x 8 chunks
            int idx = tid + i * NTHREADS;
            int row = idx >> 3, kg = idx & 7;
            cp16(sb + row * 128 + (((kg ^ (row & 7))) << 4),
                 Bp + (size_t)(n0 + row) * sB + kc + kg * 8);
        }
        asm volatile("cp.async.commit_group;");
    };

    load_stage(0, 0);

    #pragma unroll 1
    for (int i = 0; i < niter; ++i) {
        const int buf = i & 1;
        if (i + 1 < niter) {
            load_stage(buf ^ 1, i + 1);
            asm volatile("cp.async.wait_group 1;");
        } else {
            asm volatile("cp.async.wait_group 0;");
        }
        __syncthreads();

        const uint32_t sa = sbase + buf * STAGE;
        const uint32_t sb = sa + STAGE_A;
        const int tile = lane >> 3;
        const int lr   = lane & 7;

        #pragma unroll
        for (int ks = 0; ks < 4; ++ks) {                 // 4 k16 steps per BK=64
            uint32_t a[4][4];
            #pragma unroll
            for (int mi = 0; mi < 4; ++mi) {
                // x4 tiles: [r0-8,klow][r8-16,klow][r0-8,khigh][r8-16,khigh]
                int row = wm * 64 + mi * 16 + ((tile & 1) << 3) + lr;
                int kg  = 2 * ks + (tile >> 1);
                ldmatrix_x4(a[mi], sa + row * 128 + ((kg ^ (row & 7)) << 4));
            }
            uint32_t b[2][4];
            #pragma unroll
            for (int nj = 0; nj < 2; ++nj) {
                // x4 tiles: [n0-8,klow][n0-8,khigh][n8-16,klow][n8-16,khigh]
                int row = wn * 32 + nj * 16 + ((tile >> 1) << 3) + lr;
                int kg  = 2 * ks + (tile & 1);
                ldmatrix_x4(b[nj], sb + row * 128 + ((kg ^ (row & 7)) << 4));
            }
            #pragma unroll
            for (int mi = 0; mi < 4; ++mi)
                #pragma unroll
                for (int nj = 0; nj < 2; ++nj) {
                    mma16816(c[mi][nj * 2 + 0], a[mi], b[nj][0], b[nj][1]);
                    mma16816(c[mi][nj * 2 + 1], a[mi], b[nj][2], b[nj][3]);
                }
        }
        __syncthreads();
    }

    // epilogue
    #pragma unroll
    for (int mi = 0; mi < 4; ++mi) {
        const int r0 = m0 + wm * 64 + mi * 16 + (lane >> 2);
        #pragma unroll
        for (int n8 = 0; n8 < 4; ++n8) {
            const int col = n0 + wn * 32 + n8 * 8 + ((lane & 3) << 1);
            float bx = 0.0f, by = 0.0f;
            if (bias) { bx = bias[col]; by = bias[col + 1]; }
            float2 v0 = make_float2(c[mi][n8][0] + bx, c[mi][n8][1] + by);
            float2 v1 = make_float2(c[mi][n8][2] + bx, c[mi][n8][3] + by);
            *(float2*)&C[(size_t)r0 * sC + col]       = v0;
            *(float2*)&C[(size_t)(r0 + 8) * sC + col] = v1;
        }
    }
}

// ---------------- elementwise kernels ----------------
__device__ __forceinline__ float sigf(float x) { return 1.0f / (1.0f + __expf(-x)); }

__device__ __forceinline__ void split_store4(float4 v, __nv_bfloat16* hi, __nv_bfloat16* lo) {
    __nv_bfloat16 h0 = __float2bfloat16(v.x), h1 = __float2bfloat16(v.y);
    __nv_bfloat16 h2 = __float2bfloat16(v.z), h3 = __float2bfloat16(v.w);
    __nv_bfloat16 l0 = __float2bfloat16(v.x - __bfloat162float(h0));
    __nv_bfloat16 l1 = __float2bfloat16(v.y - __bfloat162float(h1));
    __nv_bfloat16 l2 = __float2bfloat16(v.z - __bfloat162float(h2));
    __nv_bfloat16 l3 = __float2bfloat16(v.w - __bfloat162float(h3));
    ((__nv_bfloat162*)hi)[0] = __nv_bfloat162(h0, h1);
    ((__nv_bfloat162*)hi)[1] = __nv_bfloat162(h2, h3);
    ((__nv_bfloat162*)lo)[0] = __nv_bfloat162(l0, l1);
    ((__nv_bfloat162*)lo)[1] = __nv_bfloat162(l2, l3);
}

// gates [B,1024] + biases -> h (fp32), c (fp32), and h hi/lo into act cols 0-255
__global__ void __launch_bounds__(256) gate_kernel(
    const float* __restrict__ gates, const float* __restrict__ c_in,
    const float* __restrict__ bi, const float* __restrict__ bh,
    float* __restrict__ h_out, float* __restrict__ c_out)
{
    int t  = blockIdx.x * blockDim.x + threadIdx.x;     // over B*H/4
    int b  = t >> 6;
    int c4 = (t & 63) << 2;
    const float* g = gates + (size_t)b * G4 + c4;
    float4 vi = *(const float4*)(g);
    float4 vf = *(const float4*)(g + 256);
    float4 vg = *(const float4*)(g + 512);
    float4 vo = *(const float4*)(g + 768);
    float4 bii = *(const float4*)(bi + c4),       bhi = *(const float4*)(bh + c4);
    float4 bif = *(const float4*)(bi + c4 + 256), bhf = *(const float4*)(bh + c4 + 256);
    float4 big = *(const float4*)(bi + c4 + 512), bhg = *(const float4*)(bh + c4 + 512);
    float4 bio = *(const float4*)(bi + c4 + 768), bho = *(const float4*)(bh + c4 + 768);
    float4 cin = *(const float4*)(c_in + (size_t)b * HH + c4);

    float4 cc, hh;
    {
        float ci = sigf(vi.x + bii.x + bhi.x), cf = sigf(vf.x + bif.x + bhf.x);
        float cg = tanhf(vg.x + big.x + bhg.x), co = sigf(vo.x + bio.x + bho.x);
        cc.x = cf * cin.x + ci * cg; hh.x = co * tanhf(cc.x);
    }
    {
        float ci = sigf(vi.y + bii.y + bhi.y), cf = sigf(vf.y + bif.y + bhf.y);
        float cg = tanhf(vg.y + big.y + bhg.y), co = sigf(vo.y + bio.y + bho.y);
        cc.y = cf * cin.y + ci * cg; hh.y = co * tanhf(cc.y);
    }
    {
        float ci = sigf(vi.z + bii.z + bhi.z), cf = sigf(vf.z + bif.z + bhf.z);
        float cg = tanhf(vg.z + big.z + bhg.z), co = sigf(vo.z + bio.z + bho.z);
        cc.z = cf * cin.z + ci * cg; hh.z = co * tanhf(cc.z);
    }
    {
        float ci = sigf(vi.w + bii.w + bhi.w), cf = sigf(vf.w + bif.w + bhf.w);
        float cg = tanhf(vg.w + big.w + bhg.w), co = sigf(vo.w + bio.w + bho.w);
        cc.w = cf * cin.w + ci * cg; hh.w = co * tanhf(cc.w);
    }
    *(float4*)(c_out + (size_t)b * HH + c4) = cc;
    *(float4*)(h_out + (size_t)b * HH + c4) = hh;
    split_store4(hh, &g_ahi[(size_t)b * KT + c4], &g_alo[(size_t)b * KT + c4]);
}

// x [B,256] -> act hi/lo cols 0-255
__global__ void __launch_bounds__(256) conv_x(const float* __restrict__ x) {
    int t = blockIdx.x * blockDim.x + threadIdx.x;
    int b = t >> 6, c4 = (t & 63) << 2;
    float4 v = *(const float4*)(x + (size_t)b * HH + c4);
    split_store4(v, &g_ahi[(size_t)b * KT + c4], &g_alo[(size_t)b * KT + c4]);
}

// h_all[l] [B,256] -> act hi/lo cols 256-511
__global__ void __launch_bounds__(256) conv_h(const float* __restrict__ hsrc) {
    int t = blockIdx.x * blockDim.x + threadIdx.x;
    int b = t >> 6, c4 = (t & 63) << 2;
    float4 v = *(const float4*)(hsrc + (size_t)b * HH + c4);
    split_store4(v, &g_ahi[(size_t)b * KT + 256 + c4], &g_alo[(size_t)b * KT + 256 + c4]);
}

// weights: [8][1024][512] = [Wih_l | Whh_l] concat along K, split hi/lo
__global__ void __launch_bounds__(256) conv_w(
    const float* __restrict__ Wih0, const float* __restrict__ Whh0,
    const float* __restrict__ Wih,  const float* __restrict__ Whh)
{
    int t  = blockIdx.x * blockDim.x + threadIdx.x;     // 1048576
    int k4 = (t & 127) << 2;
    int n  = (t >> 7) & 1023;
    int l  = t >> 17;
    const float* src;
    if (l == 0) src = (k4 < 256) ? (Wih0 + (size_t)n * 256 + k4)
                                 : (Whh0 + (size_t)n * 256 + (k4 - 256));
    else        src = (k4 < 256) ? (Wih + ((size_t)(l - 1) * G4 + n) * 256 + k4)
                                 : (Whh + ((size_t)(l - 1) * G4 + n) * 256 + (k4 - 256));
    float4 v = *(const float4*)src;
    size_t d = ((size_t)l * G4 + n) * KT + k4;
    split_store4(v, &g_whi[d], &g_wlo[d]);
}

__global__ void __launch_bounds__(256) conv_wout(const float* __restrict__ Wout) {
    int t = blockIdx.x * blockDim.x + threadIdx.x;      // 16384
    int n = t >> 6, k4 = (t & 63) << 2;
    float4 v = *(const float4*)(Wout + (size_t)n * HH + k4);
    split_store4(v, &g_wouthi[(size_t)n * HH + k4], &g_woutlo[(size_t)n * HH + k4]);
}

// ---------------- launch ----------------
extern "C" void kernel_launch(void* const* d_in, const int* in_sizes, int n_in,
                              void* d_out, int out_size)
{
    const float* x     = (const float*)d_in[0];
    const float* h_all = (const float*)d_in[1];
    const float* c_all = (const float*)d_in[2];
    const float* Wih0  = (const float*)d_in[3];
    const float* Whh0  = (const float*)d_in[4];
    const float* bih0  = (const float*)d_in[5];
    const float* bhh0  = (const float*)d_in[6];
    const float* Wih   = (const float*)d_in[7];
    const float* Whh   = (const float*)d_in[8];
    const float* bih   = (const float*)d_in[9];
    const float* bhh   = (const float*)d_in[10];
    const float* Wout  = (const float*)d_in[11];
    const float* bout  = (const float*)d_in[12];

    float* out = (float*)d_out;
    float* hs  = out + (size_t)BB * OUTF;
    float* cs  = hs + (size_t)(LL + 1) * BB * HH;

    float *gates;  __nv_bfloat16 *ahi, *alo, *whi, *wlo, *wouthi, *woutlo;
    cudaGetSymbolAddress((void**)&gates,  g_gates);
    cudaGetSymbolAddress((void**)&ahi,    g_ahi);
    cudaGetSymbolAddress((void**)&alo,    g_alo);
    cudaGetSymbolAddress((void**)&whi,    g_whi);
    cudaGetSymbolAddress((void**)&wlo,    g_wlo);
    cudaGetSymbolAddress((void**)&wouthi, g_wouthi);
    cudaGetSymbolAddress((void**)&woutlo, g_woutlo);

    cudaFuncSetAttribute(mma_gemm, cudaFuncAttributeMaxDynamicSharedMemorySize, SMEMSZ);

    const int eb = (BB * HH / 4) / 256;   // 4096 blocks for elementwise over B*H

    conv_w<<<(8 * G4 * KT / 4) / 256, 256>>>(Wih0, Whh0, Wih, Whh);
    conv_wout<<<(HH * HH / 4) / 256, 256>>>(Wout);
    conv_x<<<eb, 256>>>(x);

    for (int l = 0; l <= LL; ++l) {
        conv_h<<<eb, 256>>>(h_all + (size_t)l * BB * HH);
        mma_gemm<<<dim3(G4 / TN, BB / TM), NTHREADS, SMEMSZ>>>(
            ahi, alo, KT,
            whi + (size_t)l * G4 * KT, wlo + (size_t)l * G4 * KT, KT,
            KT, nullptr, gates, G4);
        const float* bi = (l == 0) ? bih0 : bih + (size_t)(l - 1) * G4;
        const float* bh = (l == 0) ? bhh0 : bhh + (size_t)(l - 1) * G4;
        gate_kernel<<<eb, 256>>>(gates, c_all + (size_t)l * BB * HH, bi, bh,
                                 hs + (size_t)l * BB * HH, cs + (size_t)l * BB * HH);
    }

    // output = h_last @ Wout.T + bout   (h_last hi/lo live in act cols 0-255)
    mma_gemm<<<dim3(OUTF / TN, BB / TM), NTHREADS, SMEMSZ>>>(
        ahi, alo, KT, wouthi, woutlo, HH,
        HH, bout, out, OUTF);
}